// round 13
// baseline (speedup 1.0000x reference)
#include <cuda_runtime.h>
#include <cuda_bf16.h>
#include <cstddef>

// Problem constants
#define Hh   512
#define INPS 2048
#define FS   1536
#define Bb   128
#define Tt   64
#define MROWS (Bb * Tt)          // 8192

// Persistent-recurrence tiling
#define NC   16                  // hidden cols per CTA (48 gate-cols)
#define BBB  32                  // batch rows per CTA
#define STEP_THREADS 256
#define HS   516                 // h_sm row stride (conflict-free frag LDS)
#define GHS  50                  // gh_sm row stride (48 + 2 pad)

// Scratch (device statics: allocation-free)
__device__ float g_gi[(size_t)MROWS * (3 * Hh)];       // [B*T, 1536]
__device__ float g_gf[(size_t)MROWS * (2 * Hh)];       // [B*T, 1024]
__device__ unsigned int g_hbuf[2][Bb][Hh];             // tf32 h, double-buffered
__device__ unsigned int g_barg[4];                     // per-batch-group barrier counters

// Pre-converted tf32 operands, k-pair-interleaved within each 8-col group
__device__ unsigned int g_feat1_t[(size_t)MROWS * INPS];
__device__ unsigned int g_wih_t[(size_t)(3 * Hh) * INPS];
__device__ unsigned int g_feat0_t[(size_t)MROWS * FS];
__device__ unsigned int g_wfh_t[(size_t)(2 * Hh) * FS];

__device__ __forceinline__ unsigned int f2tf32(float x) {
    unsigned int u;
    asm("cvt.rna.tf32.f32 %0, %1;" : "=r"(u) : "f"(x));
    return u;
}

// ---------------------------------------------------------------------------
// Convert fp32 -> tf32 with within-8 k-interleave: new{0..7} = old{0,4,1,5,2,6,3,7}.
// Each thread handles one 8-element group (2 float4 in, 2 uint4 out).
// ---------------------------------------------------------------------------
__global__ __launch_bounds__(256)
void cvt_permute_kernel(const float* __restrict__ in,
                        unsigned int* __restrict__ outp,
                        long ngroups)
{
    long g = blockIdx.x * 256L + threadIdx.x;
    long stride = (long)gridDim.x * 256L;
    for (; g < ngroups; g += stride) {
        const float4 v0 = *(const float4*)(in + g * 8);
        const float4 v1 = *(const float4*)(in + g * 8 + 4);
        uint4 o0, o1;
        o0.x = f2tf32(v0.x); o0.y = f2tf32(v1.x);
        o0.z = f2tf32(v0.y); o0.w = f2tf32(v1.y);
        o1.x = f2tf32(v0.z); o1.y = f2tf32(v1.z);
        o1.z = f2tf32(v0.w); o1.w = f2tf32(v1.w);
        *(uint4*)(outp + g * 8)     = o0;
        *(uint4*)(outp + g * 8 + 4) = o1;
    }
}

// ---------------------------------------------------------------------------
// Dual TF32 GEMM, 3-stage cp.async pipeline, PRE-CONVERTED permuted operands:
// consumer does zero cvt; fragment loads are LDS.64 pairs.
// Blocks [0,768):   GEMM1  M=8192 N=1536 K=2048
// Blocks [768,1280): GEMM2 M=8192 N=1024 K=1536
// ---------------------------------------------------------------------------
#define GSTRIDE 36                       // 32 + 4 pad (words per row)
#define TILE_W  (128 * GSTRIDE)
#define STAGE_W (2 * TILE_W)
#define NSTAGE  3

__global__ __launch_bounds__(256, 2)
void tf32_gemm_dual_kernel(const unsigned int* __restrict__ A1,
                           const unsigned int* __restrict__ W1,
                           const float* __restrict__ bias1, float* __restrict__ C1,
                           const unsigned int* __restrict__ A2,
                           const unsigned int* __restrict__ W2,
                           const float* __restrict__ bias2, float* __restrict__ C2)
{
    extern __shared__ unsigned int smf[];

    const int bid = blockIdx.x;
    const unsigned int *A, *W;
    const float* bias;
    float* C;
    int N, K, bm, bn;
    if (bid < 768) {
        A = A1; W = W1; bias = bias1; C = C1;
        N = 3 * Hh; K = INPS;
        bn = bid % 12; bm = bid / 12;
    } else {
        const int b2 = bid - 768;
        A = A2; W = W2; bias = bias2; C = C2;
        N = 2 * Hh; K = FS;
        bn = b2 % 8; bm = b2 / 8;
    }

    const int tid  = threadIdx.x;
    const int lane = tid & 31;
    const int warp = tid >> 5;
    const int gid  = lane >> 2;
    const int tig  = lane & 3;
    const int wm   = warp >> 2;
    const int wn   = warp & 3;

    const unsigned int* Ablk = A + (size_t)bm * 128 * K;
    const unsigned int* Wblk = W + (size_t)bn * 128 * K;

    const unsigned int smem_base =
        (unsigned int)__cvta_generic_to_shared(smf);

    const int srow = tid >> 3;
    const int sc4  = tid & 7;

    float acc[4][4][4];
#pragma unroll
    for (int i = 0; i < 4; i++)
#pragma unroll
        for (int j = 0; j < 4; j++)
#pragma unroll
            for (int f = 0; f < 4; f++) acc[i][j][f] = 0.0f;

    const int KT = K >> 5;

    auto issue_tile = [&](int kt, int stage) {
        const int k0 = kt << 5;
        const unsigned int sA = smem_base + (stage * STAGE_W) * 4;
        const unsigned int sW = sA + TILE_W * 4;
#pragma unroll
        for (int i = 0; i < 4; i++) {
            const int row = srow + i * 32;
            const unsigned int off = (row * GSTRIDE + sc4 * 4) * 4;
            const unsigned int* ga = Ablk + (size_t)row * K + k0 + sc4 * 4;
            const unsigned int* gw = Wblk + (size_t)row * K + k0 + sc4 * 4;
            asm volatile("cp.async.ca.shared.global [%0], [%1], 16;\n"
                         :: "r"(sA + off), "l"(ga));
            asm volatile("cp.async.ca.shared.global [%0], [%1], 16;\n"
                         :: "r"(sW + off), "l"(gw));
        }
    };

    issue_tile(0, 0);
    asm volatile("cp.async.commit_group;\n");
    issue_tile(1, 1);
    asm volatile("cp.async.commit_group;\n");

    for (int kt = 0; kt < KT; kt++) {
        asm volatile("cp.async.wait_group 1;\n");
        __syncthreads();

        if (kt + 2 < KT)
            issue_tile(kt + 2, (kt + 2) % NSTAGE);
        asm volatile("cp.async.commit_group;\n");

        const unsigned int* Asb = smf + ((kt % NSTAGE) * STAGE_W);
        const unsigned int* Wsb = Asb + TILE_W;

#pragma unroll
        for (int kk = 0; kk < 32; kk += 8) {
            // A fragments: pairs (tig, tig+4) adjacent after permutation
            uint2 av0[4], av1[4];
#pragma unroll
            for (int mt = 0; mt < 4; mt++) {
                const int r0 = wm * 64 + mt * 16 + gid;
                av0[mt] = *(const uint2*)&Asb[r0 * GSTRIDE + kk + 2 * tig];
                av1[mt] = *(const uint2*)&Asb[(r0 + 8) * GSTRIDE + kk + 2 * tig];
            }
            uint2 bv[4];
#pragma unroll
            for (int nt = 0; nt < 4; nt++) {
                const int n0 = wn * 32 + nt * 8 + gid;
                bv[nt] = *(const uint2*)&Wsb[n0 * GSTRIDE + kk + 2 * tig];
            }
#pragma unroll
            for (int mt = 0; mt < 4; mt++)
#pragma unroll
                for (int nt = 0; nt < 4; nt++) {
                    asm volatile(
                        "mma.sync.aligned.m16n8k8.row.col.f32.tf32.tf32.f32 "
                        "{%0,%1,%2,%3}, {%4,%5,%6,%7}, {%8,%9}, {%0,%1,%2,%3};\n"
                        : "+f"(acc[mt][nt][0]), "+f"(acc[mt][nt][1]),
                          "+f"(acc[mt][nt][2]), "+f"(acc[mt][nt][3])
                        : "r"(av0[mt].x), "r"(av1[mt].x),
                          "r"(av0[mt].y), "r"(av1[mt].y),
                          "r"(bv[nt].x), "r"(bv[nt].y));
                }
        }
        __syncthreads();
    }

#pragma unroll
    for (int mt = 0; mt < 4; mt++) {
        const int row = bm * 128 + wm * 64 + mt * 16 + gid;
#pragma unroll
        for (int nt = 0; nt < 4; nt++) {
            const int col = bn * 128 + wn * 32 + nt * 8 + tig * 2;
            const float b0 = bias[col], b1 = bias[col + 1];
            float2 v0 = make_float2(acc[mt][nt][0] + b0, acc[mt][nt][1] + b1);
            float2 v1 = make_float2(acc[mt][nt][2] + b0, acc[mt][nt][3] + b1);
            *(float2*)(C + (size_t)row * N + col)       = v0;
            *(float2*)(C + (size_t)(row + 8) * N + col) = v1;
        }
    }
}

// ---------------------------------------------------------------------------
// Persistent GRU recurrence (unchanged from R12):
//  - 4 independent 32-CTA group barriers; tf32 double-buffered h scratch;
//  - hprev in registers; gate prefetch before barrier; 2 k-half acc sets.
// ---------------------------------------------------------------------------
__global__ __launch_bounds__(STEP_THREADS, 1)
void gru_persistent_kernel(const float* __restrict__ gi,     // [B*T, 1536]
                           const float* __restrict__ gf,     // [B*T, 1024]
                           const float* __restrict__ W_hh,   // [1536, 512]
                           const float* __restrict__ b_hh,   // [1536]
                           float* __restrict__ out)          // eo [B,T,H] then hT [B,H]
{
    extern __shared__ unsigned int smu[];
    unsigned int* h_sm  = smu;                         // [32][HS] tf32 bits
    float*        gh_sm = (float*)(smu + BBB * HS);    // [32][GHS]

    const int tid  = threadIdx.x;
    const int lane = tid & 31;
    const int warp = tid >> 5;            // 0..7
    const int gid  = lane >> 2;           // 0..7
    const int tig  = lane & 3;            // 0..3
    const int c    = tid & (NC - 1);      // 0..15
    const int bg   = tid >> 4;            // 0..15
    const int colBase = blockIdx.x * NC;  // 0..496
    const int grp     = blockIdx.y;       // batch group 0..3
    const int bBase   = grp * BBB;        // 0..96
    const int n = colBase + c;

    // ---- One-time: W_hh slice -> registers as tf32 B-fragments ----
    unsigned int wb0[64], wb1[64];
    if (warp < 6) {
        const float* Wg = W_hh +
            ((size_t)((warp >> 1) * Hh + colBase + (warp & 1) * 8 + gid)) * Hh;
#pragma unroll
        for (int ks = 0; ks < 64; ks++) {
            wb0[ks] = f2tf32(Wg[ks * 8 + tig]);
            wb1[ks] = f2tf32(Wg[ks * 8 + tig + 4]);
        }
    }

    const float bhr = b_hh[n];
    const float bhi = b_hh[Hh + n];
    const float bhn = b_hh[2 * Hh + n];

    const int b0 = bBase + bg * 2;
    const int b1 = b0 + 1;

    float gir[2][3], gfr[2][2];
    float hpr[2] = {0.0f, 0.0f};
    {
        const size_t gib0 = ((size_t)b0 * Tt) * (3 * Hh);
        const size_t gfb0 = ((size_t)b0 * Tt) * (2 * Hh);
        const size_t gib1 = ((size_t)b1 * Tt) * (3 * Hh);
        const size_t gfb1 = ((size_t)b1 * Tt) * (2 * Hh);
        gir[0][0] = gi[gib0 + n];          gir[1][0] = gi[gib1 + n];
        gir[0][1] = gi[gib0 + Hh + n];     gir[1][1] = gi[gib1 + Hh + n];
        gir[0][2] = gi[gib0 + 2 * Hh + n]; gir[1][2] = gi[gib1 + 2 * Hh + n];
        gfr[0][0] = gf[gfb0 + n];          gfr[1][0] = gf[gfb1 + n];
        gfr[0][1] = gf[gfb0 + Hh + n];     gfr[1][1] = gf[gfb1 + Hh + n];
    }

    for (int t = 0; t < Tt; t++) {
        // ---- Stage h_{t-1} (tf32 bits) into smem ----
        if (t == 0) {
            uint4 z = make_uint4(0u, 0u, 0u, 0u);
#pragma unroll
            for (int i = 0; i < 16; i++) {
                int idx = tid + i * STEP_THREADS;
                int bl = idx >> 7;
                int kq = idx & 127;
                *(uint4*)(h_sm + bl * HS + kq * 4) = z;
            }
        } else {
            const unsigned int* src = &g_hbuf[(t & 1) ^ 1][bBase][0];
#pragma unroll
            for (int i = 0; i < 16; i++) {
                int idx = tid + i * STEP_THREADS;
                int bl = idx >> 7;
                int kq = idx & 127;
                uint4 v = *(const uint4*)(src + (size_t)bl * Hh + kq * 4);
                *(uint4*)(h_sm + bl * HS + kq * 4) = v;
            }
        }
        __syncthreads();

        // ---- Tensor-core gh: [32,48] = h[32,512] @ Wslice[48,512]^T ----
        if (warp < 6) {
            float acc[2][2][4];
#pragma unroll
            for (int kh = 0; kh < 2; kh++)
#pragma unroll
                for (int mt = 0; mt < 2; mt++)
#pragma unroll
                    for (int f = 0; f < 4; f++) acc[kh][mt][f] = 0.0f;

#pragma unroll
            for (int ks2 = 0; ks2 < 32; ks2++) {
#pragma unroll
                for (int kh = 0; kh < 2; kh++) {
                    const int ks = kh * 32 + ks2;
                    const int kk = ks * 8;
#pragma unroll
                    for (int mt = 0; mt < 2; mt++) {
                        const unsigned int* p = h_sm + (mt * 16 + gid) * HS + kk + tig;
                        unsigned int a0 = p[0];
                        unsigned int a1 = p[8 * HS];
                        unsigned int a2 = p[4];
                        unsigned int a3 = p[8 * HS + 4];
                        asm volatile(
                            "mma.sync.aligned.m16n8k8.row.col.f32.tf32.tf32.f32 "
                            "{%0,%1,%2,%3}, {%4,%5,%6,%7}, {%8,%9}, {%0,%1,%2,%3};\n"
                            : "+f"(acc[kh][mt][0]), "+f"(acc[kh][mt][1]),
                              "+f"(acc[kh][mt][2]), "+f"(acc[kh][mt][3])
                            : "r"(a0), "r"(a1), "r"(a2), "r"(a3),
                              "r"(wb0[ks]), "r"(wb1[ks]));
                    }
                }
            }
#pragma unroll
            for (int mt = 0; mt < 2; mt++) {
                int r = mt * 16 + gid;
                *(float2*)(gh_sm + (size_t)r * GHS + warp * 8 + tig * 2) =
                    make_float2(acc[0][mt][0] + acc[1][mt][0],
                                acc[0][mt][1] + acc[1][mt][1]);
                *(float2*)(gh_sm + (size_t)(r + 8) * GHS + warp * 8 + tig * 2) =
                    make_float2(acc[0][mt][2] + acc[1][mt][2],
                                acc[0][mt][3] + acc[1][mt][3]);
            }
        }
        __syncthreads();

        // ---- Gates + state update ----
#pragma unroll
        for (int j = 0; j < 2; j++) {
            const int bl = bg * 2 + j;
            const int b  = bBase + bl;

            float ghr = gh_sm[(size_t)bl * GHS + c]          + bhr;
            float ghi = gh_sm[(size_t)bl * GHS + NC + c]     + bhi;
            float ghn = gh_sm[(size_t)bl * GHS + 2 * NC + c] + bhn;

            float xr = gir[j][0] + ghr + gfr[j][0];
            float xi = gir[j][1] + ghi + gfr[j][1];
            float resetgate = 1.0f / (1.0f + expf(-xr));
            float inputgate = 1.0f / (1.0f + expf(-xi));
            float newgate   = tanhf(gir[j][2] + resetgate * ghn);

            float hy = newgate + inputgate * (hpr[j] - newgate);
            hpr[j] = hy;

            out[((size_t)b * Tt + t) * Hh + n] = hy;
            g_hbuf[t & 1][b][n] = f2tf32(hy);
            if (t == Tt - 1)
                out[(size_t)Bb * Tt * Hh + (size_t)b * Hh + n] = hy;
        }

        // ---- Prefetch next step's gates (hidden under barrier spin) ----
        if (t + 1 < Tt) {
            const size_t gib0 = ((size_t)b0 * Tt + t + 1) * (3 * Hh);
            const size_t gfb0 = ((size_t)b0 * Tt + t + 1) * (2 * Hh);
            const size_t gib1 = ((size_t)b1 * Tt + t + 1) * (3 * Hh);
            const size_t gfb1 = ((size_t)b1 * Tt + t + 1) * (2 * Hh);
            gir[0][0] = gi[gib0 + n];          gir[1][0] = gi[gib1 + n];
            gir[0][1] = gi[gib0 + Hh + n];     gir[1][1] = gi[gib1 + Hh + n];
            gir[0][2] = gi[gib0 + 2 * Hh + n]; gir[1][2] = gi[gib1 + 2 * Hh + n];
            gfr[0][0] = gf[gfb0 + n];          gfr[1][0] = gf[gfb1 + n];
            gfr[0][1] = gf[gfb0 + Hh + n];     gfr[1][1] = gf[gfb1 + Hh + n];
        }

        // ---- Group barrier: only the 32 CTAs sharing this batch group ----
        __threadfence();
        __syncthreads();
        if (tid == 0) {
            unsigned int old  = atomicAdd(&g_barg[grp], 1u);
            unsigned int need = (old / 32u + 1u) * 32u;
            while (true) {
                unsigned int cur;
                asm volatile("ld.acquire.gpu.u32 %0, [%1];"
                             : "=r"(cur) : "l"(&g_barg[grp]));
                if (cur >= need) break;
            }
            __threadfence();
        }
        __syncthreads();
    }
}

// ---------------------------------------------------------------------------
// Launch
// ---------------------------------------------------------------------------
extern "C" void kernel_launch(void* const* d_in, const int* in_sizes, int n_in,
                              void* d_out, int out_size)
{
    const float* feat0 = (const float*)d_in[0];   // [B,T,FS]
    const float* feat1 = (const float*)d_in[1];   // [B,T,IN]
    const float* W_ih  = (const float*)d_in[2];   // [3H, IN]
    const float* b_ih  = (const float*)d_in[3];   // [3H]
    const float* W_hh  = (const float*)d_in[4];   // [3H, H]
    const float* b_hh  = (const float*)d_in[5];   // [3H]
    const float* W_fh  = (const float*)d_in[6];   // [2H, FS]
    const float* b_fh  = (const float*)d_in[7];   // [2H]
    float* out = (float*)d_out;

    float *gi_ptr, *gf_ptr;
    cudaGetSymbolAddress((void**)&gi_ptr, g_gi);
    cudaGetSymbolAddress((void**)&gf_ptr, g_gf);
    unsigned int *f1t, *wiht, *f0t, *wfht;
    cudaGetSymbolAddress((void**)&f1t,  g_feat1_t);
    cudaGetSymbolAddress((void**)&wiht, g_wih_t);
    cudaGetSymbolAddress((void**)&f0t,  g_feat0_t);
    cudaGetSymbolAddress((void**)&wfht, g_wfh_t);

    // Pre-convert all GEMM operands to permuted tf32 (one cheap pass)
    cvt_permute_kernel<<<4096, 256>>>(feat1, f1t,  (long)MROWS * INPS / 8);
    cvt_permute_kernel<<<1024, 256>>>(W_ih,  wiht, (long)(3 * Hh) * INPS / 8);
    cvt_permute_kernel<<<4096, 256>>>(feat0, f0t,  (long)MROWS * FS / 8);
    cvt_permute_kernel<<<1024, 256>>>(W_fh,  wfht, (long)(2 * Hh) * FS / 8);

    // Both projection GEMMs in ONE fused launch (cvt-free consumer path)
    {
        const int smem_bytes = NSTAGE * STAGE_W * (int)sizeof(float); // 110592
        cudaFuncSetAttribute(tf32_gemm_dual_kernel,
                             cudaFuncAttributeMaxDynamicSharedMemorySize, smem_bytes);
        tf32_gemm_dual_kernel<<<1280, 256, smem_bytes>>>(
            f1t, wiht, b_ih, gi_ptr,
            f0t, wfht, b_fh, gf_ptr);
    }
    // Recurrence: single persistent kernel, tensor-core gh, 64 steps internally
    {
        const int smem_bytes = (BBB * HS + BBB * GHS) * (int)sizeof(float); // 72448
        cudaFuncSetAttribute(gru_persistent_kernel,
                             cudaFuncAttributeMaxDynamicSharedMemorySize, smem_bytes);
        dim3 grid(Hh / NC, Bb / BBB);   // (32, 4) = 128 CTAs
        gru_persistent_kernel<<<grid, STEP_THREADS, smem_bytes>>>(
            gi_ptr, gf_ptr, W_hh, b_hh, out);
    }
}

// round 14
// speedup vs baseline: 1.0150x; 1.0150x over previous
#include <cuda_runtime.h>
#include <cuda_bf16.h>
#include <cstddef>

// Problem constants
#define Hh   512
#define INPS 2048
#define FS   1536
#define Bb   128
#define Tt   64
#define MROWS (Bb * Tt)          // 8192

// Persistent-recurrence tiling
#define NC   16                  // hidden cols per CTA (48 gate-cols)
#define BBB  32                  // batch rows per CTA
#define STEP_THREADS 256
#define HS   516                 // h_sm row stride (conflict-free frag LDS)
#define GHS  50                  // gh_sm row stride (48 + 2 pad)

// Persistent-GEMM scheduling
#define GEMM_CTAS 296            // 2 per SM, all co-resident
#define NTILES    1280           // 768 (GEMM1) + 512 (GEMM2)

// Scratch (device statics: allocation-free)
__device__ float g_gi[(size_t)MROWS * (3 * Hh)];       // [B*T, 1536]
__device__ float g_gf[(size_t)MROWS * (2 * Hh)];       // [B*T, 1024]
__device__ unsigned int g_hbuf[2][Bb][Hh];             // tf32 h, double-buffered
__device__ unsigned int g_barg[4];                     // per-batch-group barrier counters

__device__ __forceinline__ unsigned int f2tf32(float x) {
    unsigned int u;
    asm("cvt.rna.tf32.f32 %0, %1;" : "=r"(u) : "f"(x));
    return u;
}

// ---------------------------------------------------------------------------
// PERSISTENT dual TF32 GEMM, 3-stage cp.async pipeline.
//   C[M,N] = A[M,K] * W[N,K]^T + bias[N]
// Logical tiles [0,768):   GEMM1  M=8192 N=1536 K=2048
// Logical tiles [768,1280): GEMM2 M=8192 N=1024 K=1536
// 296 CTAs, each processes tiles  bid, bid+296, ...  -> no wave quantization.
// CTA tile 128x128, BK=32, 8 warps (2x4), warp tile 64x32 = 4x4 m16n8k8.
// fp32 lands in smem via cp.async; cvt.rna on fragment path.
// ---------------------------------------------------------------------------
#define GSTRIDE 36                       // 32 + 4 pad (fp32 words per row)
#define TILE_W  (128 * GSTRIDE)
#define STAGE_W (2 * TILE_W)
#define NSTAGE  3

__global__ __launch_bounds__(256, 2)
void tf32_gemm_dual_kernel(const float* __restrict__ A1, const float* __restrict__ W1,
                           const float* __restrict__ bias1, float* __restrict__ C1,
                           const float* __restrict__ A2, const float* __restrict__ W2,
                           const float* __restrict__ bias2, float* __restrict__ C2)
{
    extern __shared__ float smf[];

    const int tid  = threadIdx.x;
    const int lane = tid & 31;
    const int warp = tid >> 5;
    const int gid  = lane >> 2;
    const int tig  = lane & 3;
    const int wm   = warp >> 2;
    const int wn   = warp & 3;

    const unsigned int smem_base =
        (unsigned int)__cvta_generic_to_shared(smf);

    const int srow = tid >> 3;           // staging row (0..31), +32*i
    const int sc4  = tid & 7;

    for (int tileId = blockIdx.x; tileId < NTILES; tileId += GEMM_CTAS) {
        // ---- Resolve logical tile ----
        const float *A, *W, *bias;
        float* C;
        int N, K, bm, bn;
        if (tileId < 768) {
            A = A1; W = W1; bias = bias1; C = C1;
            N = 3 * Hh; K = INPS;
            bn = tileId % 12; bm = tileId / 12;
        } else {
            const int b2 = tileId - 768;
            A = A2; W = W2; bias = bias2; C = C2;
            N = 2 * Hh; K = FS;
            bn = b2 % 8; bm = b2 / 8;
        }

        const float* Ablk = A + (size_t)bm * 128 * K;
        const float* Wblk = W + (size_t)bn * 128 * K;
        const int KT = K >> 5;

        auto issue_tile = [&](int kt, int stage) {
            const int k0 = kt << 5;
            const unsigned int sA = smem_base + (stage * STAGE_W) * 4;
            const unsigned int sW = sA + TILE_W * 4;
#pragma unroll
            for (int i = 0; i < 4; i++) {
                const int row = srow + i * 32;
                const unsigned int off = (row * GSTRIDE + sc4 * 4) * 4;
                const float* ga = Ablk + (size_t)row * K + k0 + sc4 * 4;
                const float* gw = Wblk + (size_t)row * K + k0 + sc4 * 4;
                asm volatile("cp.async.ca.shared.global [%0], [%1], 16;\n"
                             :: "r"(sA + off), "l"(ga));
                asm volatile("cp.async.ca.shared.global [%0], [%1], 16;\n"
                             :: "r"(sW + off), "l"(gw));
            }
        };

        float acc[4][4][4];
#pragma unroll
        for (int i = 0; i < 4; i++)
#pragma unroll
            for (int j = 0; j < 4; j++)
#pragma unroll
                for (int f = 0; f < 4; f++) acc[i][j][f] = 0.0f;

        // Prologue: tiles 0 and 1 in flight
        issue_tile(0, 0);
        asm volatile("cp.async.commit_group;\n");
        issue_tile(1, 1);
        asm volatile("cp.async.commit_group;\n");

        for (int kt = 0; kt < KT; kt++) {
            asm volatile("cp.async.wait_group 1;\n");
            __syncthreads();

            if (kt + 2 < KT)
                issue_tile(kt + 2, (kt + 2) % NSTAGE);
            asm volatile("cp.async.commit_group;\n");

            const float* Asb = smf + ((kt % NSTAGE) * STAGE_W);
            const float* Wsb = Asb + TILE_W;

#pragma unroll
            for (int kk = 0; kk < 32; kk += 8) {
                unsigned int af[4][4];
#pragma unroll
                for (int mt = 0; mt < 4; mt++) {
                    const int r0 = wm * 64 + mt * 16 + gid;
                    const float* p = &Asb[r0 * GSTRIDE + kk + tig];
                    af[mt][0] = f2tf32(p[0]);
                    af[mt][1] = f2tf32(p[8 * GSTRIDE]);
                    af[mt][2] = f2tf32(p[4]);
                    af[mt][3] = f2tf32(p[8 * GSTRIDE + 4]);
                }
                unsigned int bf[4][2];
#pragma unroll
                for (int nt = 0; nt < 4; nt++) {
                    const int n0 = wn * 32 + nt * 8 + gid;
                    const float* p = &Wsb[n0 * GSTRIDE + kk + tig];
                    bf[nt][0] = f2tf32(p[0]);
                    bf[nt][1] = f2tf32(p[4]);
                }
#pragma unroll
                for (int mt = 0; mt < 4; mt++)
#pragma unroll
                    for (int nt = 0; nt < 4; nt++) {
                        asm volatile(
                            "mma.sync.aligned.m16n8k8.row.col.f32.tf32.tf32.f32 "
                            "{%0,%1,%2,%3}, {%4,%5,%6,%7}, {%8,%9}, {%0,%1,%2,%3};\n"
                            : "+f"(acc[mt][nt][0]), "+f"(acc[mt][nt][1]),
                              "+f"(acc[mt][nt][2]), "+f"(acc[mt][nt][3])
                            : "r"(af[mt][0]), "r"(af[mt][1]),
                              "r"(af[mt][2]), "r"(af[mt][3]),
                              "r"(bf[nt][0]), "r"(bf[nt][1]));
                    }
            }
            __syncthreads();
        }

        // Epilogue: bias + store (registers only -> safe before next tile)
#pragma unroll
        for (int mt = 0; mt < 4; mt++) {
            const int row = bm * 128 + wm * 64 + mt * 16 + gid;
#pragma unroll
            for (int nt = 0; nt < 4; nt++) {
                const int col = bn * 128 + wn * 32 + nt * 8 + tig * 2;
                const float b0 = bias[col], b1 = bias[col + 1];
                float2 v0 = make_float2(acc[mt][nt][0] + b0, acc[mt][nt][1] + b1);
                float2 v1 = make_float2(acc[mt][nt][2] + b0, acc[mt][nt][3] + b1);
                *(float2*)(C + (size_t)row * N + col)       = v0;
                *(float2*)(C + (size_t)(row + 8) * N + col) = v1;
            }
        }
    }
}

// ---------------------------------------------------------------------------
// Persistent GRU recurrence (unchanged from R12 — best known):
//  - 4 independent 32-CTA group barriers; tf32 double-buffered h scratch;
//  - hprev in registers; gate prefetch before barrier; 2 k-half acc sets.
// ---------------------------------------------------------------------------
__global__ __launch_bounds__(STEP_THREADS, 1)
void gru_persistent_kernel(const float* __restrict__ gi,     // [B*T, 1536]
                           const float* __restrict__ gf,     // [B*T, 1024]
                           const float* __restrict__ W_hh,   // [1536, 512]
                           const float* __restrict__ b_hh,   // [1536]
                           float* __restrict__ out)          // eo [B,T,H] then hT [B,H]
{
    extern __shared__ unsigned int smu[];
    unsigned int* h_sm  = smu;                         // [32][HS] tf32 bits
    float*        gh_sm = (float*)(smu + BBB * HS);    // [32][GHS]

    const int tid  = threadIdx.x;
    const int lane = tid & 31;
    const int warp = tid >> 5;            // 0..7
    const int gid  = lane >> 2;           // 0..7
    const int tig  = lane & 3;            // 0..3
    const int c    = tid & (NC - 1);      // 0..15
    const int bg   = tid >> 4;            // 0..15
    const int colBase = blockIdx.x * NC;  // 0..496
    const int grp     = blockIdx.y;       // batch group 0..3
    const int bBase   = grp * BBB;        // 0..96
    const int n = colBase + c;

    // ---- One-time: W_hh slice -> registers as tf32 B-fragments ----
    unsigned int wb0[64], wb1[64];
    if (warp < 6) {
        const float* Wg = W_hh +
            ((size_t)((warp >> 1) * Hh + colBase + (warp & 1) * 8 + gid)) * Hh;
#pragma unroll
        for (int ks = 0; ks < 64; ks++) {
            wb0[ks] = f2tf32(Wg[ks * 8 + tig]);
            wb1[ks] = f2tf32(Wg[ks * 8 + tig + 4]);
        }
    }

    const float bhr = b_hh[n];
    const float bhi = b_hh[Hh + n];
    const float bhn = b_hh[2 * Hh + n];

    const int b0 = bBase + bg * 2;
    const int b1 = b0 + 1;

    float gir[2][3], gfr[2][2];
    float hpr[2] = {0.0f, 0.0f};
    {
        const size_t gib0 = ((size_t)b0 * Tt) * (3 * Hh);
        const size_t gfb0 = ((size_t)b0 * Tt) * (2 * Hh);
        const size_t gib1 = ((size_t)b1 * Tt) * (3 * Hh);
        const size_t gfb1 = ((size_t)b1 * Tt) * (2 * Hh);
        gir[0][0] = gi[gib0 + n];          gir[1][0] = gi[gib1 + n];
        gir[0][1] = gi[gib0 + Hh + n];     gir[1][1] = gi[gib1 + Hh + n];
        gir[0][2] = gi[gib0 + 2 * Hh + n]; gir[1][2] = gi[gib1 + 2 * Hh + n];
        gfr[0][0] = gf[gfb0 + n];          gfr[1][0] = gf[gfb1 + n];
        gfr[0][1] = gf[gfb0 + Hh + n];     gfr[1][1] = gf[gfb1 + Hh + n];
    }

    for (int t = 0; t < Tt; t++) {
        // ---- Stage h_{t-1} (tf32 bits) into smem ----
        if (t == 0) {
            uint4 z = make_uint4(0u, 0u, 0u, 0u);
#pragma unroll
            for (int i = 0; i < 16; i++) {
                int idx = tid + i * STEP_THREADS;
                int bl = idx >> 7;
                int kq = idx & 127;
                *(uint4*)(h_sm + bl * HS + kq * 4) = z;
            }
        } else {
            const unsigned int* src = &g_hbuf[(t & 1) ^ 1][bBase][0];
#pragma unroll
            for (int i = 0; i < 16; i++) {
                int idx = tid + i * STEP_THREADS;
                int bl = idx >> 7;
                int kq = idx & 127;
                uint4 v = *(const uint4*)(src + (size_t)bl * Hh + kq * 4);
                *(uint4*)(h_sm + bl * HS + kq * 4) = v;
            }
        }
        __syncthreads();

        // ---- Tensor-core gh: [32,48] = h[32,512] @ Wslice[48,512]^T ----
        if (warp < 6) {
            float acc[2][2][4];
#pragma unroll
            for (int kh = 0; kh < 2; kh++)
#pragma unroll
                for (int mt = 0; mt < 2; mt++)
#pragma unroll
                    for (int f = 0; f < 4; f++) acc[kh][mt][f] = 0.0f;

#pragma unroll
            for (int ks2 = 0; ks2 < 32; ks2++) {
#pragma unroll
                for (int kh = 0; kh < 2; kh++) {
                    const int ks = kh * 32 + ks2;
                    const int kk = ks * 8;
#pragma unroll
                    for (int mt = 0; mt < 2; mt++) {
                        const unsigned int* p = h_sm + (mt * 16 + gid) * HS + kk + tig;
                        unsigned int a0 = p[0];
                        unsigned int a1 = p[8 * HS];
                        unsigned int a2 = p[4];
                        unsigned int a3 = p[8 * HS + 4];
                        asm volatile(
                            "mma.sync.aligned.m16n8k8.row.col.f32.tf32.tf32.f32 "
                            "{%0,%1,%2,%3}, {%4,%5,%6,%7}, {%8,%9}, {%0,%1,%2,%3};\n"
                            : "+f"(acc[kh][mt][0]), "+f"(acc[kh][mt][1]),
                              "+f"(acc[kh][mt][2]), "+f"(acc[kh][mt][3])
                            : "r"(a0), "r"(a1), "r"(a2), "r"(a3),
                              "r"(wb0[ks]), "r"(wb1[ks]));
                    }
                }
            }
#pragma unroll
            for (int mt = 0; mt < 2; mt++) {
                int r = mt * 16 + gid;
                *(float2*)(gh_sm + (size_t)r * GHS + warp * 8 + tig * 2) =
                    make_float2(acc[0][mt][0] + acc[1][mt][0],
                                acc[0][mt][1] + acc[1][mt][1]);
                *(float2*)(gh_sm + (size_t)(r + 8) * GHS + warp * 8 + tig * 2) =
                    make_float2(acc[0][mt][2] + acc[1][mt][2],
                                acc[0][mt][3] + acc[1][mt][3]);
            }
        }
        __syncthreads();

        // ---- Gates + state update ----
#pragma unroll
        for (int j = 0; j < 2; j++) {
            const int bl = bg * 2 + j;
            const int b  = bBase + bl;

            float ghr = gh_sm[(size_t)bl * GHS + c]          + bhr;
            float ghi = gh_sm[(size_t)bl * GHS + NC + c]     + bhi;
            float ghn = gh_sm[(size_t)bl * GHS + 2 * NC + c] + bhn;

            float xr = gir[j][0] + ghr + gfr[j][0];
            float xi = gir[j][1] + ghi + gfr[j][1];
            float resetgate = 1.0f / (1.0f + expf(-xr));
            float inputgate = 1.0f / (1.0f + expf(-xi));
            float newgate   = tanhf(gir[j][2] + resetgate * ghn);

            float hy = newgate + inputgate * (hpr[j] - newgate);
            hpr[j] = hy;

            out[((size_t)b * Tt + t) * Hh + n] = hy;
            g_hbuf[t & 1][b][n] = f2tf32(hy);
            if (t == Tt - 1)
                out[(size_t)Bb * Tt * Hh + (size_t)b * Hh + n] = hy;
        }

        // ---- Prefetch next step's gates (hidden under barrier spin) ----
        if (t + 1 < Tt) {
            const size_t gib0 = ((size_t)b0 * Tt + t + 1) * (3 * Hh);
            const size_t gfb0 = ((size_t)b0 * Tt + t + 1) * (2 * Hh);
            const size_t gib1 = ((size_t)b1 * Tt + t + 1) * (3 * Hh);
            const size_t gfb1 = ((size_t)b1 * Tt + t + 1) * (2 * Hh);
            gir[0][0] = gi[gib0 + n];          gir[1][0] = gi[gib1 + n];
            gir[0][1] = gi[gib0 + Hh + n];     gir[1][1] = gi[gib1 + Hh + n];
            gir[0][2] = gi[gib0 + 2 * Hh + n]; gir[1][2] = gi[gib1 + 2 * Hh + n];
            gfr[0][0] = gf[gfb0 + n];          gfr[1][0] = gf[gfb1 + n];
            gfr[0][1] = gf[gfb0 + Hh + n];     gfr[1][1] = gf[gfb1 + Hh + n];
        }

        // ---- Group barrier: only the 32 CTAs sharing this batch group ----
        __threadfence();
        __syncthreads();
        if (tid == 0) {
            unsigned int old  = atomicAdd(&g_barg[grp], 1u);
            unsigned int need = (old / 32u + 1u) * 32u;
            while (true) {
                unsigned int cur;
                asm volatile("ld.acquire.gpu.u32 %0, [%1];"
                             : "=r"(cur) : "l"(&g_barg[grp]));
                if (cur >= need) break;
            }
            __threadfence();
        }
        __syncthreads();
    }
}

// ---------------------------------------------------------------------------
// Launch
// ---------------------------------------------------------------------------
extern "C" void kernel_launch(void* const* d_in, const int* in_sizes, int n_in,
                              void* d_out, int out_size)
{
    const float* feat0 = (const float*)d_in[0];   // [B,T,FS]
    const float* feat1 = (const float*)d_in[1];   // [B,T,IN]
    const float* W_ih  = (const float*)d_in[2];   // [3H, IN]
    const float* b_ih  = (const float*)d_in[3];   // [3H]
    const float* W_hh  = (const float*)d_in[4];   // [3H, H]
    const float* b_hh  = (const float*)d_in[5];   // [3H]
    const float* W_fh  = (const float*)d_in[6];   // [2H, FS]
    const float* b_fh  = (const float*)d_in[7];   // [2H]
    float* out = (float*)d_out;

    float *gi_ptr, *gf_ptr;
    cudaGetSymbolAddress((void**)&gi_ptr, g_gi);
    cudaGetSymbolAddress((void**)&gf_ptr, g_gf);

    // Both projection GEMMs: ONE persistent launch (296 CTAs, 1280 tiles)
    {
        const int smem_bytes = NSTAGE * STAGE_W * (int)sizeof(float); // 110592
        cudaFuncSetAttribute(tf32_gemm_dual_kernel,
                             cudaFuncAttributeMaxDynamicSharedMemorySize, smem_bytes);
        tf32_gemm_dual_kernel<<<GEMM_CTAS, 256, smem_bytes>>>(
            feat1, W_ih, b_ih, gi_ptr,
            feat0, W_fh, b_fh, gf_ptr);
    }
    // Recurrence: single persistent kernel, tensor-core gh, 64 steps internally
    {
        const int smem_bytes = (BBB * HS + BBB * GHS) * (int)sizeof(float); // 72448
        cudaFuncSetAttribute(gru_persistent_kernel,
                             cudaFuncAttributeMaxDynamicSharedMemorySize, smem_bytes);
        dim3 grid(Hh / NC, Bb / BBB);   // (32, 4) = 128 CTAs
        gru_persistent_kernel<<<grid, STEP_THREADS, smem_bytes>>>(
            gi_ptr, gf_ptr, W_hh, b_hh, out);
    }
}

// round 16
// speedup vs baseline: 1.1903x; 1.1727x over previous
#include <cuda_runtime.h>
#include <cuda_bf16.h>
#include <cstddef>

// Problem constants
#define Hh   512
#define INPS 2048
#define FS   1536
#define Bb   128
#define Tt   64
#define MROWS (Bb * Tt)          // 8192

// Persistent-recurrence tiling
#define NC   16                  // hidden cols per CTA (48 gate-cols)
#define BBB  32                  // batch rows per CTA
#define STEP_THREADS 256
#define HS   516                 // h_sm row stride (conflict-free frag LDS)
#define GHS  50                  // gh_sm row stride (48 + 2 pad)

// Scratch (device statics: allocation-free)
__device__ float g_gi[(size_t)MROWS * (3 * Hh)];       // [B*T, 1536]
__device__ float g_gf[(size_t)MROWS * (2 * Hh)];       // [B*T, 1024]
__device__ unsigned int g_hbuf[2][Bb][Hh];             // tf32 h, double-buffered
__device__ unsigned int g_barg[4];                     // per-batch-group barrier counters

__device__ __forceinline__ unsigned int f2tf32(float x) {
    unsigned int u;
    asm("cvt.rna.tf32.f32 %0, %1;" : "=r"(u) : "f"(x));
    return u;
}

// ---------------------------------------------------------------------------
// Dual TF32 GEMM, 3-stage cp.async.cg pipeline (L1-bypass), one sync per tile.
//   C[M,N] = A[M,K] * W[N,K]^T + bias[N]
// Blocks [0,768):   GEMM1  M=8192 N=1536 K=2048
// Blocks [768,1280): GEMM2 M=8192 N=1024 K=1536
// CTA tile 128x128, BK=32, 8 warps (2x4), warp tile 64x32 = 4x4 m16n8k8.
// fp32 lands in smem via cp.async.cg; cvt.rna on fragment path.
// ---------------------------------------------------------------------------
#define GSTRIDE 36                       // 32 + 4 pad (fp32 words per row)
#define TILE_W  (128 * GSTRIDE)
#define STAGE_W (2 * TILE_W)
#define NSTAGE  3

__global__ __launch_bounds__(256, 2)
void tf32_gemm_dual_kernel(const float* __restrict__ A1, const float* __restrict__ W1,
                           const float* __restrict__ bias1, float* __restrict__ C1,
                           const float* __restrict__ A2, const float* __restrict__ W2,
                           const float* __restrict__ bias2, float* __restrict__ C2)
{
    extern __shared__ float smf[];

    const int bid = blockIdx.x;
    const float *A, *W, *bias;
    float* C;
    int N, K, bm, bn;
    if (bid < 768) {
        A = A1; W = W1; bias = bias1; C = C1;
        N = 3 * Hh; K = INPS;
        bn = bid % 12; bm = bid / 12;
    } else {
        const int b2 = bid - 768;
        A = A2; W = W2; bias = bias2; C = C2;
        N = 2 * Hh; K = FS;
        bn = b2 % 8; bm = b2 / 8;
    }

    const int tid  = threadIdx.x;
    const int lane = tid & 31;
    const int warp = tid >> 5;
    const int gid  = lane >> 2;
    const int tig  = lane & 3;
    const int wm   = warp >> 2;
    const int wn   = warp & 3;

    const float* Ablk = A + (size_t)bm * 128 * K;
    const float* Wblk = W + (size_t)bn * 128 * K;

    const unsigned int smem_base =
        (unsigned int)__cvta_generic_to_shared(smf);

    const int srow = tid >> 3;           // staging row (0..31), +32*i
    const int sc4  = tid & 7;

    float acc[4][4][4];
#pragma unroll
    for (int i = 0; i < 4; i++)
#pragma unroll
        for (int j = 0; j < 4; j++)
#pragma unroll
            for (int f = 0; f < 4; f++) acc[i][j][f] = 0.0f;

    const int KT = K >> 5;

    auto issue_tile = [&](int kt, int stage) {
        const int k0 = kt << 5;
        const unsigned int sA = smem_base + (stage * STAGE_W) * 4;
        const unsigned int sW = sA + TILE_W * 4;
#pragma unroll
        for (int i = 0; i < 4; i++) {
            const int row = srow + i * 32;
            const unsigned int off = (row * GSTRIDE + sc4 * 4) * 4;
            const float* ga = Ablk + (size_t)row * K + k0 + sc4 * 4;
            const float* gw = Wblk + (size_t)row * K + k0 + sc4 * 4;
            asm volatile("cp.async.cg.shared.global [%0], [%1], 16;\n"
                         :: "r"(sA + off), "l"(ga));
            asm volatile("cp.async.cg.shared.global [%0], [%1], 16;\n"
                         :: "r"(sW + off), "l"(gw));
        }
    };

    issue_tile(0, 0);
    asm volatile("cp.async.commit_group;\n");
    issue_tile(1, 1);
    asm volatile("cp.async.commit_group;\n");

    for (int kt = 0; kt < KT; kt++) {
        asm volatile("cp.async.wait_group 1;\n");
        __syncthreads();                 // all copies for tile kt visible;
                                         // also: all warps done with tile kt-1's MMA

        if (kt + 2 < KT)
            issue_tile(kt + 2, (kt + 2) % NSTAGE);
        asm volatile("cp.async.commit_group;\n");

        const float* Asb = smf + ((kt % NSTAGE) * STAGE_W);
        const float* Wsb = Asb + TILE_W;

#pragma unroll
        for (int kk = 0; kk < 32; kk += 8) {
            unsigned int af[4][4];
#pragma unroll
            for (int mt = 0; mt < 4; mt++) {
                const int r0 = wm * 64 + mt * 16 + gid;
                const float* p = &Asb[r0 * GSTRIDE + kk + tig];
                af[mt][0] = f2tf32(p[0]);
                af[mt][1] = f2tf32(p[8 * GSTRIDE]);
                af[mt][2] = f2tf32(p[4]);
                af[mt][3] = f2tf32(p[8 * GSTRIDE + 4]);
            }
            unsigned int bf[4][2];
#pragma unroll
            for (int nt = 0; nt < 4; nt++) {
                const int n0 = wn * 32 + nt * 8 + gid;
                const float* p = &Wsb[n0 * GSTRIDE + kk + tig];
                bf[nt][0] = f2tf32(p[0]);
                bf[nt][1] = f2tf32(p[4]);
            }
#pragma unroll
            for (int mt = 0; mt < 4; mt++)
#pragma unroll
                for (int nt = 0; nt < 4; nt++) {
                    asm volatile(
                        "mma.sync.aligned.m16n8k8.row.col.f32.tf32.tf32.f32 "
                        "{%0,%1,%2,%3}, {%4,%5,%6,%7}, {%8,%9}, {%0,%1,%2,%3};\n"
                        : "+f"(acc[mt][nt][0]), "+f"(acc[mt][nt][1]),
                          "+f"(acc[mt][nt][2]), "+f"(acc[mt][nt][3])
                        : "r"(af[mt][0]), "r"(af[mt][1]),
                          "r"(af[mt][2]), "r"(af[mt][3]),
                          "r"(bf[nt][0]), "r"(bf[nt][1]));
                }
        }
        // NOTE: no trailing __syncthreads — next iteration's wait_group +
        // __syncthreads provides the needed cross-warp ordering before any
        // cp.async overwrites a stage.
    }

    // Epilogue: bias + store
#pragma unroll
    for (int mt = 0; mt < 4; mt++) {
        const int row = bm * 128 + wm * 64 + mt * 16 + gid;
#pragma unroll
        for (int nt = 0; nt < 4; nt++) {
            const int col = bn * 128 + wn * 32 + nt * 8 + tig * 2;
            const float b0 = bias[col], b1 = bias[col + 1];
            float2 v0 = make_float2(acc[mt][nt][0] + b0, acc[mt][nt][1] + b1);
            float2 v1 = make_float2(acc[mt][nt][2] + b0, acc[mt][nt][3] + b1);
            *(float2*)(C + (size_t)row * N + col)       = v0;
            *(float2*)(C + (size_t)(row + 8) * N + col) = v1;
        }
    }
}

// ---------------------------------------------------------------------------
// Persistent GRU recurrence (R12 structure):
//  - 4 independent 32-CTA group barriers; tf32 double-buffered h scratch;
//  - hprev in registers; gate prefetch + fp32 out-stores moved AFTER the
//    barrier arrive (hidden under spin; fence only covers the 2 hbuf words).
// ---------------------------------------------------------------------------
__global__ __launch_bounds__(STEP_THREADS, 1)
void gru_persistent_kernel(const float* __restrict__ gi,     // [B*T, 1536]
                           const float* __restrict__ gf,     // [B*T, 1024]
                           const float* __restrict__ W_hh,   // [1536, 512]
                           const float* __restrict__ b_hh,   // [1536]
                           float* __restrict__ out)          // eo [B,T,H] then hT [B,H]
{
    extern __shared__ unsigned int smu[];
    unsigned int* h_sm  = smu;                         // [32][HS] tf32 bits
    float*        gh_sm = (float*)(smu + BBB * HS);    // [32][GHS]

    const int tid  = threadIdx.x;
    const int lane = tid & 31;
    const int warp = tid >> 5;            // 0..7
    const int gid  = lane >> 2;           // 0..7
    const int tig  = lane & 3;            // 0..3
    const int c    = tid & (NC - 1);      // 0..15
    const int bg   = tid >> 4;            // 0..15
    const int colBase = blockIdx.x * NC;  // 0..496
    const int grp     = blockIdx.y;       // batch group 0..3
    const int bBase   = grp * BBB;        // 0..96
    const int n = colBase + c;

    // ---- One-time: W_hh slice -> registers as tf32 B-fragments ----
    unsigned int wb0[64], wb1[64];
    if (warp < 6) {
        const float* Wg = W_hh +
            ((size_t)((warp >> 1) * Hh + colBase + (warp & 1) * 8 + gid)) * Hh;
#pragma unroll
        for (int ks = 0; ks < 64; ks++) {
            wb0[ks] = f2tf32(Wg[ks * 8 + tig]);
            wb1[ks] = f2tf32(Wg[ks * 8 + tig + 4]);
        }
    }

    const float bhr = b_hh[n];
    const float bhi = b_hh[Hh + n];
    const float bhn = b_hh[2 * Hh + n];

    const int b0 = bBase + bg * 2;
    const int b1 = b0 + 1;

    float gir[2][3], gfr[2][2];
    float hpr[2] = {0.0f, 0.0f};
    {
        const size_t gib0 = ((size_t)b0 * Tt) * (3 * Hh);
        const size_t gfb0 = ((size_t)b0 * Tt) * (2 * Hh);
        const size_t gib1 = ((size_t)b1 * Tt) * (3 * Hh);
        const size_t gfb1 = ((size_t)b1 * Tt) * (2 * Hh);
        gir[0][0] = gi[gib0 + n];          gir[1][0] = gi[gib1 + n];
        gir[0][1] = gi[gib0 + Hh + n];     gir[1][1] = gi[gib1 + Hh + n];
        gir[0][2] = gi[gib0 + 2 * Hh + n]; gir[1][2] = gi[gib1 + 2 * Hh + n];
        gfr[0][0] = gf[gfb0 + n];          gfr[1][0] = gf[gfb1 + n];
        gfr[0][1] = gf[gfb0 + Hh + n];     gfr[1][1] = gf[gfb1 + Hh + n];
    }

    for (int t = 0; t < Tt; t++) {
        // ---- Stage h_{t-1} (tf32 bits) into smem ----
        if (t == 0) {
            uint4 z = make_uint4(0u, 0u, 0u, 0u);
#pragma unroll
            for (int i = 0; i < 16; i++) {
                int idx = tid + i * STEP_THREADS;
                int bl = idx >> 7;
                int kq = idx & 127;
                *(uint4*)(h_sm + bl * HS + kq * 4) = z;
            }
        } else {
            const unsigned int* src = &g_hbuf[(t & 1) ^ 1][bBase][0];
#pragma unroll
            for (int i = 0; i < 16; i++) {
                int idx = tid + i * STEP_THREADS;
                int bl = idx >> 7;
                int kq = idx & 127;
                uint4 v = *(const uint4*)(src + (size_t)bl * Hh + kq * 4);
                *(uint4*)(h_sm + bl * HS + kq * 4) = v;
            }
        }
        __syncthreads();

        // ---- Tensor-core gh: [32,48] = h[32,512] @ Wslice[48,512]^T ----
        if (warp < 6) {
            float acc[2][2][4];
#pragma unroll
            for (int kh = 0; kh < 2; kh++)
#pragma unroll
                for (int mt = 0; mt < 2; mt++)
#pragma unroll
                    for (int f = 0; f < 4; f++) acc[kh][mt][f] = 0.0f;

#pragma unroll
            for (int ks2 = 0; ks2 < 32; ks2++) {
#pragma unroll
                for (int kh = 0; kh < 2; kh++) {
                    const int ks = kh * 32 + ks2;
                    const int kk = ks * 8;
#pragma unroll
                    for (int mt = 0; mt < 2; mt++) {
                        const unsigned int* p = h_sm + (mt * 16 + gid) * HS + kk + tig;
                        unsigned int a0 = p[0];
                        unsigned int a1 = p[8 * HS];
                        unsigned int a2 = p[4];
                        unsigned int a3 = p[8 * HS + 4];
                        asm volatile(
                            "mma.sync.aligned.m16n8k8.row.col.f32.tf32.tf32.f32 "
                            "{%0,%1,%2,%3}, {%4,%5,%6,%7}, {%8,%9}, {%0,%1,%2,%3};\n"
                            : "+f"(acc[kh][mt][0]), "+f"(acc[kh][mt][1]),
                              "+f"(acc[kh][mt][2]), "+f"(acc[kh][mt][3])
                            : "r"(a0), "r"(a1), "r"(a2), "r"(a3),
                              "r"(wb0[ks]), "r"(wb1[ks]));
                    }
                }
            }
#pragma unroll
            for (int mt = 0; mt < 2; mt++) {
                int r = mt * 16 + gid;
                *(float2*)(gh_sm + (size_t)r * GHS + warp * 8 + tig * 2) =
                    make_float2(acc[0][mt][0] + acc[1][mt][0],
                                acc[0][mt][1] + acc[1][mt][1]);
                *(float2*)(gh_sm + (size_t)(r + 8) * GHS + warp * 8 + tig * 2) =
                    make_float2(acc[0][mt][2] + acc[1][mt][2],
                                acc[0][mt][3] + acc[1][mt][3]);
            }
        }
        __syncthreads();

        // ---- Gates + state update: compute hy, store ONLY hbuf (exchange) ----
        float hy[2];
#pragma unroll
        for (int j = 0; j < 2; j++) {
            const int bl = bg * 2 + j;
            const int b  = bBase + bl;

            float ghr = gh_sm[(size_t)bl * GHS + c]          + bhr;
            float ghi = gh_sm[(size_t)bl * GHS + NC + c]     + bhi;
            float ghn = gh_sm[(size_t)bl * GHS + 2 * NC + c] + bhn;

            float xr = gir[j][0] + ghr + gfr[j][0];
            float xi = gir[j][1] + ghi + gfr[j][1];
            float resetgate = 1.0f / (1.0f + expf(-xr));
            float inputgate = 1.0f / (1.0f + expf(-xi));
            float newgate   = tanhf(gir[j][2] + resetgate * ghn);

            hy[j] = newgate + inputgate * (hpr[j] - newgate);
            hpr[j] = hy[j];

            g_hbuf[t & 1][b][n] = f2tf32(hy[j]);
        }

        // ---- Make hbuf visible, then arrive at the group barrier ----
        __threadfence();
        __syncthreads();
        unsigned int need = 0;
        if (tid == 0) {
            unsigned int old = atomicAdd(&g_barg[grp], 1u);
            need = (old / 32u + 1u) * 32u;
        }

        // ---- Off-critical-path work while peers arrive:
        //      fp32 output stores + next step's gate prefetch ----
#pragma unroll
        for (int j = 0; j < 2; j++) {
            const int b = bBase + bg * 2 + j;
            out[((size_t)b * Tt + t) * Hh + n] = hy[j];
            if (t == Tt - 1)
                out[(size_t)Bb * Tt * Hh + (size_t)b * Hh + n] = hy[j];
        }
        if (t + 1 < Tt) {
            const size_t gib0 = ((size_t)b0 * Tt + t + 1) * (3 * Hh);
            const size_t gfb0 = ((size_t)b0 * Tt + t + 1) * (2 * Hh);
            const size_t gib1 = ((size_t)b1 * Tt + t + 1) * (3 * Hh);
            const size_t gfb1 = ((size_t)b1 * Tt + t + 1) * (2 * Hh);
            gir[0][0] = gi[gib0 + n];          gir[1][0] = gi[gib1 + n];
            gir[0][1] = gi[gib0 + Hh + n];     gir[1][1] = gi[gib1 + Hh + n];
            gir[0][2] = gi[gib0 + 2 * Hh + n]; gir[1][2] = gi[gib1 + 2 * Hh + n];
            gfr[0][0] = gf[gfb0 + n];          gfr[1][0] = gf[gfb1 + n];
            gfr[0][1] = gf[gfb0 + Hh + n];     gfr[1][1] = gf[gfb1 + Hh + n];
        }

        // ---- Spin until all 32 group CTAs arrived ----
        if (tid == 0) {
            while (true) {
                unsigned int cur;
                asm volatile("ld.acquire.gpu.u32 %0, [%1];"
                             : "=r"(cur) : "l"(&g_barg[grp]));
                if (cur >= need) break;
            }
            __threadfence();
        }
        __syncthreads();
    }
}

// ---------------------------------------------------------------------------
// Launch
// ---------------------------------------------------------------------------
extern "C" void kernel_launch(void* const* d_in, const int* in_sizes, int n_in,
                              void* d_out, int out_size)
{
    const float* feat0 = (const float*)d_in[0];   // [B,T,FS]
    const float* feat1 = (const float*)d_in[1];   // [B,T,IN]
    const float* W_ih  = (const float*)d_in[2];   // [3H, IN]
    const float* b_ih  = (const float*)d_in[3];   // [3H]
    const float* W_hh  = (const float*)d_in[4];   // [3H, H]
    const float* b_hh  = (const float*)d_in[5];   // [3H]
    const float* W_fh  = (const float*)d_in[6];   // [2H, FS]
    const float* b_fh  = (const float*)d_in[7];   // [2H]
    float* out = (float*)d_out;

    float *gi_ptr, *gf_ptr;
    cudaGetSymbolAddress((void**)&gi_ptr, g_gi);
    cudaGetSymbolAddress((void**)&gf_ptr, g_gf);

    // Both projection GEMMs in ONE fused launch (tf32 + cp.async.cg pipeline)
    {
        const int smem_bytes = NSTAGE * STAGE_W * (int)sizeof(float); // 110592
        cudaFuncSetAttribute(tf32_gemm_dual_kernel,
                             cudaFuncAttributeMaxDynamicSharedMemorySize, smem_bytes);
        tf32_gemm_dual_kernel<<<1280, 256, smem_bytes>>>(
            feat1, W_ih, b_ih, gi_ptr,
            feat0, W_fh, b_fh, gf_ptr);
    }
    // Recurrence: single persistent kernel, tensor-core gh, 64 steps internally
    {
        const int smem_bytes = (BBB * HS + BBB * GHS) * (int)sizeof(float); // 72448
        cudaFuncSetAttribute(gru_persistent_kernel,
                             cudaFuncAttributeMaxDynamicSharedMemorySize, smem_bytes);
        dim3 grid(Hh / NC, Bb / BBB);   // (32, 4) = 128 CTAs
        gru_persistent_kernel<<<grid, STEP_THREADS, smem_bytes>>>(
            gi_ptr, gf_ptr, W_hh, b_hh, out);
    }
}